// round 13
// baseline (speedup 1.0000x reference)
#include <cuda_runtime.h>
#include <cuda_fp16.h>
#include <cstdint>

// ---------------- problem shapes ----------------
#define Bc   512
#define Sc   64
#define Nc   8
#define Ac   16
#define Hc   256
#define OBSc 512

// strides (32-bit words)
#define BSTR2 136    // uint32 words per B column (16 chunks * 8 + pad 8)
#define ATS   136    // uint32 words per staged A row in smem
#define AW    128    // uint32 words per A row in gmem

// ---------------- device scratch ----------------
__device__ __align__(16) uint32_t g_B16[2][128 * BSTR2];      // fp16x2 W2 image per n-half
__device__ __align__(16) uint32_t g_A[(size_t)Bc * 512 * AW]; // fp16x2 A = mish(h1), frag layout

// ---------------- helpers ----------------
__device__ __forceinline__ float mish_f(float x) {
    float e  = __expf(fminf(x, 15.0f));
    float u  = 1.0f + e;
    float d  = fmaf(u, u, 1.0f);
    float r  = __uint_as_float(0x7EF477D5u - __float_as_uint(d));
    r = r * (2.0f - d * r);
    r = r * (2.0f - d * r);
    return x * (1.0f - 2.0f * r);
}
__device__ __forceinline__ uint32_t h2pack(float lo, float hi) {
    uint32_t r;
    asm("cvt.rn.f16x2.f32 %0, %1, %2;" : "=r"(r) : "f"(hi), "f"(lo));
    return r;
}

#define MMA_F16(C, a0, a1, a2, a3, b0, b1)                                    \
    asm volatile("mma.sync.aligned.m16n8k16.row.col.f32.f16.f16.f32 "        \
        "{%0,%1,%2,%3}, {%4,%5,%6,%7}, {%8,%9}, {%0,%1,%2,%3};"              \
        : "+f"(C.x), "+f"(C.y), "+f"(C.z), "+f"(C.w)                         \
        : "r"(a0), "r"(a1), "r"(a2), "r"(a3), "r"(b0), "r"(b1))

// ================= prep 1: W2 -> fp16x2 packed B images =================
__global__ void prep_w2_kernel(const float* __restrict__ W2) {
    int idx = blockIdx.x * blockDim.x + threadIdx.x;   // 32768 words
    if (idx >= 2 * 128 * 128) return;
    int nhalf = idx >> 14;
    int rem   = idx & 16383;
    int col   = rem >> 7;
    int w     = rem & 127;
    int chunk = w >> 3;
    int kq    = (w >> 1) & 3;
    int hi    = w & 1;
    int k0    = chunk * 16 + hi * 8 + kq * 2;
    int n     = nhalf * 128 + col;
    g_B16[nhalf][col * BSTR2 + w] = h2pack(W2[k0 * Hc + n], W2[(k0 + 1) * Hc + n]);
}

// ================= merged prep: obs1 + PA (smem) -> A = mish(prefix) fp16 ====
#define PB_SMEM ((512 + 128 + 512 + 64 * 256 + 512) * 4)   // 72192 B
__global__ void __launch_bounds__(512, 2)
prep_bA_kernel(const float* __restrict__ state,
               const float* __restrict__ action,
               const float* __restrict__ W1,
               const float* __restrict__ b1,
               const int*   __restrict__ perm) {
    extern __shared__ float pbs[];
    float* sState = pbs;                           // 512
    float* sAct   = pbs + 512;                     // 128
    float* sObsP  = pbs + 640;                     // 512
    float* sPA    = pbs + 1152;                    // 64*256
    int*   sPerm  = (int*)(pbs + 1152 + 64 * 256); // 512
    const int tid = threadIdx.x;
    const int b   = blockIdx.x;

    sState[tid] = state[b * OBSc + tid];
    if (tid < 128) sAct[tid] = action[b * 128 + tid];
    sPerm[tid] = perm[b * 512 + tid];
    __syncthreads();

    const int h   = tid & 255;
    const int seg = tid >> 8;

    {
        float oa = 0.f, obp = 0.f, oc = 0.f, od = 0.f;
        const int kb = seg * 256;
        #pragma unroll 4
        for (int k = kb; k < kb + 256; k += 4) {
            oa  = fmaf(sState[k],     __ldg(&W1[(k)     * Hc + h]), oa);
            obp = fmaf(sState[k + 1], __ldg(&W1[(k + 1) * Hc + h]), obp);
            oc  = fmaf(sState[k + 2], __ldg(&W1[(k + 2) * Hc + h]), oc);
            od  = fmaf(sState[k + 3], __ldg(&W1[(k + 3) * Hc + h]), od);
        }
        sObsP[seg * 256 + h] = (oa + obp) + (oc + od) + (seg == 0 ? b1[h] : 0.f);
    }
    __syncthreads();
    const float ob = sObsP[h] + sObsP[256 + h];

    #pragma unroll 1
    for (int jj = 0; jj < 4; ++jj) {
        const int j = seg * 4 + jj;
        #pragma unroll 1
        for (int n = 0; n < 8; ++n) {
            float p = (j == 0) ? ob : 0.0f;
            #pragma unroll
            for (int k = 0; k < 16; ++k)
                p = fmaf(sAct[n * 16 + k],
                         __ldg(&W1[(OBSc + j * 16 + k) * Hc + h]), p);
            sPA[(j * 8 + n) * 256 + h] = p;
        }
    }
    __syncthreads();

    const int quarter = tid >> 7;
    const int wp      = tid & 127;
    const int ch      = wp >> 3;
    const int kq      = (wp >> 1) & 3;
    const int hi      = wp & 1;
    const int k0      = ch * 16 + hi * 8 + kq * 2;

    #pragma unroll 2
    for (int ss = 0; ss < 16; ++ss) {
        const int s = quarter * 16 + ss;
        float x0 = 0.f, x1 = 0.f;
        #pragma unroll
        for (int t = 0; t < 8; ++t) {
            const int row = t * 8 + sPerm[s * 8 + t];
            float2 v = *(const float2*)&sPA[row * 256 + k0];
            x0 += v.x; x1 += v.y;
            g_A[((size_t)b * 512 + t * 64 + s) * AW + wp] =
                h2pack(mish_f(x0), mish_f(x1));
        }
    }
}

// ================= main fused GEMM kernel =================
// grid 1024: (b = bx>>1, nh = bx&1). 256 threads, 8 warps, 2 CTAs/SM.
// 8 passes of 64 rows (pass p == prefix index t=p). Warp tile 32 rows x 32 cols
// (rg = wid&1, cg = wid>>1). Gather folded into the pass loop via inverse perm.
#define OFF_B     0
#define SZ_B      (128 * BSTR2 * 4)        // 69632
#define OFF_A     (OFF_B + SZ_B)           // A tile: 64 * ATS * 4 = 34816
#define OFF_PERM  (OFF_A + 34816)          // 512 ints
#define OFF_IPERM (OFF_PERM + 2048)        // 512 ints
#define OFF_RQ    (OFF_IPERM + 2048)       // 64*4 f
#define OFF_B2    (OFF_RQ + 1024)          // 128 f
#define OFF_W3    (OFF_B2 + 512)           // 128 f
#define OFF_Q1    (OFF_W3 + 512)           // 8 f
#define SMEM_MAIN (OFF_Q1 + 128)           // 110752 B -> 2 CTAs/SM

__global__ void __launch_bounds__(256, 2)
shapley_mma(const float* __restrict__ b2,
            const float* __restrict__ W3,
            const float* __restrict__ b3,
            const int*   __restrict__ perm,
            float*       __restrict__ out) {
    extern __shared__ char smem[];
    const int tid  = threadIdx.x;
    const int wid  = tid >> 5;
    const int lane = tid & 31;
    const int b    = blockIdx.x >> 1;
    const int nh   = blockIdx.x & 1;

    uint32_t* sB  = (uint32_t*)(smem + OFF_B);
    uint32_t* sA  = (uint32_t*)(smem + OFF_A);
    int*   sPerm  = (int*)  (smem + OFF_PERM);
    int*   sIperm = (int*)  (smem + OFF_IPERM);
    float* sRQ    = (float*)(smem + OFF_RQ);
    float* sB2    = (float*)(smem + OFF_B2);
    float* sW3    = (float*)(smem + OFF_W3);
    float* sQ1    = (float*)(smem + OFF_Q1);

    // ---- stage B + perm (+inverse perm) ----
    {
        const uint4* src = (const uint4*)g_B16[nh];
        uint4* dst = (uint4*)sB;
        for (int i = tid; i < (128 * BSTR2) / 4; i += 256) dst[i] = src[i];
    }
    for (int i = tid; i < Sc * Nc; i += 256) sPerm[i] = perm[b * (Sc * Nc) + i];
    if (tid < 128) {
        sB2[tid] = b2[nh * 128 + tid];
        sW3[tid] = W3[nh * 128 + tid];
    }
    if (tid < 8) sQ1[tid] = 0.0f;
    __syncthreads();
    for (int i = tid; i < 512; i += 256) {
        int s = i >> 3, ii = i & 7;
        sIperm[s * 8 + sPerm[i]] = ii;     // perm[s, ii] = t  ->  iperm[s, t] = ii
    }
    const float b3h = 0.5f * b3[0];

    const int lam = lane >> 2;
    const int kq  = lane & 3;
    const int rg  = wid & 1;       // row group (0..1)
    const int cg  = wid >> 1;      // col group (0..3)
    const int lr  = rg * 32 + lam; // local row of first fragment

    const uint4* aSrc = (const uint4*)(g_A + ((size_t)b * 512) * AW);
    const int sr = tid >> 5, sc = tid & 31;

    uint4 st0, st1, st2, st3, st4, st5, st6, st7;
#define LDG_TILE(p) { const uint4* s_ = aSrc + (size_t)(p) * (64 * 32) + tid;  \
    st0 = s_[0];     st1 = s_[256];  st2 = s_[512];  st3 = s_[768];            \
    st4 = s_[1024];  st5 = s_[1280]; st6 = s_[1536]; st7 = s_[1792]; }
#define STS_TILE() {                                                           \
    *(uint4*)&sA[(sr +  0) * ATS + sc * 4] = st0;                              \
    *(uint4*)&sA[(sr +  8) * ATS + sc * 4] = st1;                              \
    *(uint4*)&sA[(sr + 16) * ATS + sc * 4] = st2;                              \
    *(uint4*)&sA[(sr + 24) * ATS + sc * 4] = st3;                              \
    *(uint4*)&sA[(sr + 32) * ATS + sc * 4] = st4;                              \
    *(uint4*)&sA[(sr + 40) * ATS + sc * 4] = st5;                              \
    *(uint4*)&sA[(sr + 48) * ATS + sc * 4] = st6;                              \
    *(uint4*)&sA[(sr + 56) * ATS + sc * 4] = st7; }
    LDG_TILE(0);
    __syncthreads();               // B/perm/iperm staged

    #pragma unroll 1
    for (int p = 0; p < 8; ++p) {
        STS_TILE();
        __syncthreads();           // tile visible
        if (p < 7) LDG_TILE(p + 1);

        float4 C0 = {0,0,0,0}, C1 = {0,0,0,0}, C2 = {0,0,0,0}, C3 = {0,0,0,0};
        float4 C4 = {0,0,0,0}, C5 = {0,0,0,0}, C6 = {0,0,0,0}, C7 = {0,0,0,0};

        #pragma unroll
        for (int ch = 0; ch < 16; ++ch) {
            const int aof = ch * 8 + 2 * kq;
            uint2 a0 = *(const uint2*)&sA[(lr)      * ATS + aof];
            uint2 a1 = *(const uint2*)&sA[(lr +  8) * ATS + aof];
            uint2 a2 = *(const uint2*)&sA[(lr + 16) * ATS + aof];
            uint2 a3 = *(const uint2*)&sA[(lr + 24) * ATS + aof];
#define BMMAQ(nt, nt4) { uint2 bb = *(const uint2*)&sB[((cg * 32 + (nt) * 8) + lam) * BSTR2 + aof]; \
            MMA_F16(C##nt,  a0.x, a1.x, a0.y, a1.y, bb.x, bb.y);              \
            MMA_F16(C##nt4, a2.x, a3.x, a2.y, a3.y, bb.x, bb.y); }
            BMMAQ(0, 4) BMMAQ(1, 5) BMMAQ(2, 6) BMMAQ(3, 7)
#undef BMMAQ
        }

        // ---- epilogue: mish(z+b2)*w3, 4 row-sums over this warp's 32 cols ----
        float rs0 = 0.f, rs1 = 0.f, rs2 = 0.f, rs3 = 0.f;
#define EPI2(nt, nt4) { const int c0i = cg * 32 + (nt) * 8 + kq * 2;              \
    const float w0 = sW3[c0i], w1 = sW3[c0i + 1];                                 \
    const float z0 = sB2[c0i], z1 = sB2[c0i + 1];                                 \
    rs0 += mish_f(C##nt.x  + z0) * w0 + mish_f(C##nt.y  + z1) * w1;               \
    rs1 += mish_f(C##nt.z  + z0) * w0 + mish_f(C##nt.w  + z1) * w1;               \
    rs2 += mish_f(C##nt4.x + z0) * w0 + mish_f(C##nt4.y + z1) * w1;               \
    rs3 += mish_f(C##nt4.z + z0) * w0 + mish_f(C##nt4.w + z1) * w1; }
        EPI2(0, 4) EPI2(1, 5) EPI2(2, 6) EPI2(3, 7)
#undef EPI2
        rs0 += __shfl_xor_sync(0xffffffffu, rs0, 1);
        rs0 += __shfl_xor_sync(0xffffffffu, rs0, 2);
        rs1 += __shfl_xor_sync(0xffffffffu, rs1, 1);
        rs1 += __shfl_xor_sync(0xffffffffu, rs1, 2);
        rs2 += __shfl_xor_sync(0xffffffffu, rs2, 1);
        rs2 += __shfl_xor_sync(0xffffffffu, rs2, 2);
        rs3 += __shfl_xor_sync(0xffffffffu, rs3, 1);
        rs3 += __shfl_xor_sync(0xffffffffu, rs3, 2);
        if (kq == 0) {
            sRQ[(lr)      * 4 + cg] = rs0;
            sRQ[(lr +  8) * 4 + cg] = rs1;
            sRQ[(lr + 16) * 4 + cg] = rs2;
            sRQ[(lr + 24) * 4 + cg] = rs3;
        }
        __syncthreads();           // partials visible; sA reads done

        // ---- per-pass gather: row (t=p, s) -> q1[iperm[s][p]] ----
        if (tid < 64) {
            const int s = tid;
            float q = sRQ[s * 4] + sRQ[s * 4 + 1] + sRQ[s * 4 + 2]
                    + sRQ[s * 4 + 3] + b3h;
            atomicAdd(&sQ1[sIperm[s * 8 + p]], q);
        }
        // note: next pass's "tile visible" sync orders these reads vs next writes
    }
    __syncthreads();

    if (tid < 8) {
        float q = sQ1[tid] * (1.0f / 64.0f);
        atomicAdd(&out[b * Nc + tid], q);                 // q1
        atomicAdd(&out[Bc * Nc + b * Nc + tid], q);       // duplicate half
    }
}

extern "C" void kernel_launch(void* const* d_in, const int* in_sizes, int n_in,
                              void* d_out, int out_size) {
    const float* state  = (const float*)d_in[0];
    const float* action = (const float*)d_in[1];
    const float* W1     = (const float*)d_in[2];
    const float* b1     = (const float*)d_in[3];
    const float* W2     = (const float*)d_in[4];
    const float* b2     = (const float*)d_in[5];
    const float* W3     = (const float*)d_in[6];
    const float* b3     = (const float*)d_in[7];
    const int*   perm   = (const int*)  d_in[8];
    float* out = (float*)d_out;

    cudaFuncSetAttribute(shapley_mma,
                         cudaFuncAttributeMaxDynamicSharedMemorySize, SMEM_MAIN);
    cudaFuncSetAttribute(prep_bA_kernel,
                         cudaFuncAttributeMaxDynamicSharedMemorySize, PB_SMEM);

    prep_w2_kernel<<<128, 256>>>(W2);
    prep_bA_kernel<<<Bc, 512, PB_SMEM>>>(state, action, W1, b1, perm);

    int zelems = (out_size < 2 * Bc * Nc) ? out_size : (2 * Bc * Nc);
    cudaMemsetAsync(d_out, 0, (size_t)zelems * sizeof(float), 0);

    shapley_mma<<<Bc * 2, 256, SMEM_MAIN>>>(b2, W3, b3, perm, out);
}

// round 15
// speedup vs baseline: 1.1387x; 1.1387x over previous
#include <cuda_runtime.h>
#include <cuda_fp16.h>
#include <cstdint>

// ---------------- problem shapes ----------------
#define Bc   512
#define Sc   64
#define Nc   8
#define Ac   16
#define Hc   256
#define OBSc 512

// strides (32-bit words)
#define BSTR2 136    // uint32 words per B column (16 chunks * 8 + pad 8)
#define AW    128    // uint32 words per A row in gmem

// ---------------- device scratch ----------------
__device__ __align__(16) uint32_t g_B16[2][128 * BSTR2];      // fp16x2 W2 image per n-half
__device__ __align__(16) uint32_t g_A[(size_t)Bc * 512 * AW]; // fp16x2 A = mish(h1), frag layout

// ---------------- helpers ----------------
__device__ __forceinline__ float mish_f(float x) {
    float e  = __expf(fminf(x, 15.0f));
    float u  = 1.0f + e;
    float d  = fmaf(u, u, 1.0f);
    float r  = __uint_as_float(0x7EF477D5u - __float_as_uint(d));
    r = r * (2.0f - d * r);
    r = r * (2.0f - d * r);
    return x * (1.0f - 2.0f * r);
}
__device__ __forceinline__ uint32_t h2pack(float lo, float hi) {
    uint32_t r;
    asm("cvt.rn.f16x2.f32 %0, %1, %2;" : "=r"(r) : "f"(hi), "f"(lo));
    return r;
}

#define MMA_F16(C, a0, a1, a2, a3, b0, b1)                                    \
    asm volatile("mma.sync.aligned.m16n8k16.row.col.f32.f16.f16.f32 "        \
        "{%0,%1,%2,%3}, {%4,%5,%6,%7}, {%8,%9}, {%0,%1,%2,%3};"              \
        : "+f"(C.x), "+f"(C.y), "+f"(C.z), "+f"(C.w)                         \
        : "r"(a0), "r"(a1), "r"(a2), "r"(a3), "r"(b0), "r"(b1))

// ================= prep 1: W2 -> fp16x2 packed B images =================
__global__ void prep_w2_kernel(const float* __restrict__ W2) {
    int idx = blockIdx.x * blockDim.x + threadIdx.x;   // 32768 words
    if (idx >= 2 * 128 * 128) return;
    int nhalf = idx >> 14;
    int rem   = idx & 16383;
    int col   = rem >> 7;
    int w     = rem & 127;
    int chunk = w >> 3;
    int kq    = (w >> 1) & 3;
    int hi    = w & 1;
    int k0    = chunk * 16 + hi * 8 + kq * 2;
    int n     = nhalf * 128 + col;
    g_B16[nhalf][col * BSTR2 + w] = h2pack(W2[k0 * Hc + n], W2[(k0 + 1) * Hc + n]);
}

// ================= merged prep: obs1 + PA (smem) -> A = mish(prefix) fp16 ====
// grid 512 (one b), 512 threads. Thread = (hg = tid&63 -> 4 h cols, seg = tid>>6).
#define PB_SMEM ((512 + 128 + 2048 + 64 * 256 + 512) * 4)   // 78336 B
__global__ void __launch_bounds__(512, 2)
prep_bA_kernel(const float* __restrict__ state,
               const float* __restrict__ action,
               const float* __restrict__ W1,
               const float* __restrict__ b1,
               const int*   __restrict__ perm) {
    extern __shared__ float pbs[];
    float* sState = pbs;                            // 512
    float* sAct   = pbs + 512;                      // 128
    float* sObsP  = pbs + 640;                      // 8 segs x 256 h
    float* sPA    = pbs + 2688;                     // 64*256
    int*   sPerm  = (int*)(pbs + 2688 + 64 * 256);  // 512
    const int tid = threadIdx.x;
    const int b   = blockIdx.x;

    sState[tid] = state[b * OBSc + tid];            // 512 threads = 512 elems
    if (tid < 128) sAct[tid] = action[b * 128 + tid];
    sPerm[tid] = perm[b * 512 + tid];               // FIX: all 512 entries
    __syncthreads();

    const int hg  = tid & 63;       // h group: h0 = hg*4
    const int seg = tid >> 6;       // 0..7
    const int h0  = hg * 4;

    // ---- obs1 partials: seg covers k in [seg*64, seg*64+64) ----
    {
        float p0 = 0.f, p1 = 0.f, p2 = 0.f, p3 = 0.f;
        const int kb = seg * 64;
        #pragma unroll 4
        for (int k = kb; k < kb + 64; ++k) {
            const float4 w = *(const float4*)&W1[k * Hc + h0];
            const float s = sState[k];
            p0 = fmaf(s, w.x, p0);
            p1 = fmaf(s, w.y, p1);
            p2 = fmaf(s, w.z, p2);
            p3 = fmaf(s, w.w, p3);
        }
        sObsP[seg * 256 + h0]     = p0;
        sObsP[seg * 256 + h0 + 1] = p1;
        sObsP[seg * 256 + h0 + 2] = p2;
        sObsP[seg * 256 + h0 + 3] = p3;
    }
    __syncthreads();

    // ---- ob4 = b1 + sum of 8 partials (each thread, its 4 h) ----
    float4 ob4 = *(const float4*)&b1[h0];
    #pragma unroll
    for (int sg = 0; sg < 8; ++sg) {
        ob4.x += sObsP[sg * 256 + h0];
        ob4.y += sObsP[sg * 256 + h0 + 1];
        ob4.z += sObsP[sg * 256 + h0 + 2];
        ob4.w += sObsP[sg * 256 + h0 + 3];
    }

    // ---- PA rows: thread's j = seg; W1 row reused across 8 n ----
    {
        const int j = seg;
        float4 pa0 = {0,0,0,0}, pa1 = {0,0,0,0}, pa2 = {0,0,0,0}, pa3 = {0,0,0,0};
        float4 pa4 = {0,0,0,0}, pa5 = {0,0,0,0}, pa6 = {0,0,0,0}, pa7 = {0,0,0,0};
        #pragma unroll
        for (int k = 0; k < 16; ++k) {
            const float4 w = *(const float4*)&W1[(OBSc + j * 16 + k) * Hc + h0];
#define PACC(n) { const float a = sAct[(n) * 16 + k];                          \
    pa##n.x = fmaf(a, w.x, pa##n.x); pa##n.y = fmaf(a, w.y, pa##n.y);          \
    pa##n.z = fmaf(a, w.z, pa##n.z); pa##n.w = fmaf(a, w.w, pa##n.w); }
            PACC(0) PACC(1) PACC(2) PACC(3) PACC(4) PACC(5) PACC(6) PACC(7)
#undef PACC
        }
        if (j == 0) {
#define FOLD(n) { pa##n.x += ob4.x; pa##n.y += ob4.y;                          \
                  pa##n.z += ob4.z; pa##n.w += ob4.w; }
            FOLD(0) FOLD(1) FOLD(2) FOLD(3) FOLD(4) FOLD(5) FOLD(6) FOLD(7)
#undef FOLD
        }
#define PST(n) *(float4*)&sPA[(j * 8 + (n)) * 256 + h0] = pa##n;
        PST(0) PST(1) PST(2) PST(3) PST(4) PST(5) PST(6) PST(7)
#undef PST
    }
    __syncthreads();

    // ---- prefix + mish + fp16 pack -> g_A (fragment word layout) ----
    const int quarter = tid >> 7;    // 0..3 -> s block of 16
    const int wp      = tid & 127;   // word position in A row
    const int ch      = wp >> 3;
    const int kq      = (wp >> 1) & 3;
    const int hi      = wp & 1;
    const int k0      = ch * 16 + hi * 8 + kq * 2;

    #pragma unroll 2
    for (int ss = 0; ss < 16; ++ss) {
        const int s = quarter * 16 + ss;
        float x0 = 0.f, x1 = 0.f;
        #pragma unroll
        for (int t = 0; t < 8; ++t) {
            const int row = t * 8 + sPerm[s * 8 + t];
            float2 v = *(const float2*)&sPA[row * 256 + k0];
            x0 += v.x; x1 += v.y;
            g_A[((size_t)b * 512 + t * 64 + s) * AW + wp] =
                h2pack(mish_f(x0), mish_f(x1));
        }
    }
}

// ================= main fused GEMM kernel (R11, unchanged) =================
// grid 1024: (b = bx>>1, nh = bx&1). 256 threads, 8 warps, 2 CTAs/SM.
// Warp tile: 32 rows x 64 cols (rg = wid>>1, cg = wid&1); 4 passes of 128 rows.
#define OFF_B     0
#define SZ_B      (128 * BSTR2 * 4)        // 69632
#define OFF_PERM  (OFF_B + SZ_B)           // 512 ints
#define OFF_ROWP  (OFF_PERM + 2048)        // 512*2 f
#define OFF_B2    (OFF_ROWP + 4096)        // 128 f
#define OFF_W3    (OFF_B2 + 512)           // 128 f
#define OFF_RED   (OFF_W3 + 512)           // 256 f
#define SMEM_MAIN (OFF_RED + 1024)         // 77824 B -> 2 CTAs/SM

__global__ void __launch_bounds__(256, 2)
shapley_mma(const float* __restrict__ b2,
            const float* __restrict__ W3,
            const float* __restrict__ b3,
            const int*   __restrict__ perm,
            float*       __restrict__ out) {
    extern __shared__ char smem[];
    const int tid  = threadIdx.x;
    const int wid  = tid >> 5;
    const int lane = tid & 31;
    const int b    = blockIdx.x >> 1;
    const int nh   = blockIdx.x & 1;

    uint32_t* sB = (uint32_t*)(smem + OFF_B);
    int*   sPerm = (int*)  (smem + OFF_PERM);
    float* sRowP = (float*)(smem + OFF_ROWP);
    float* sB2   = (float*)(smem + OFF_B2);
    float* sW3   = (float*)(smem + OFF_W3);
    float* sRed  = (float*)(smem + OFF_RED);

    {
        const uint4* src = (const uint4*)g_B16[nh];
        uint4* dst = (uint4*)sB;
        for (int i = tid; i < (128 * BSTR2) / 4; i += 256) dst[i] = src[i];
    }
    for (int i = tid; i < Sc * Nc; i += 256) sPerm[i] = perm[b * (Sc * Nc) + i];
    if (tid < 128) {
        sB2[tid] = b2[nh * 128 + tid];
        sW3[tid] = W3[nh * 128 + tid];
    }
    const float b3v = b3[0];
    __syncthreads();

    const int lam = lane >> 2;
    const int kq  = lane & 3;
    const int rg  = wid >> 1;      // 0..3
    const int cg  = wid & 1;       // 0..1

    #pragma unroll 1
    for (int p = 0; p < 4; ++p) {
        const int r0 = p * 128 + rg * 32 + lam;
        const uint32_t* aR = g_A + ((size_t)b * 512 + r0) * AW + 2 * kq;

        float4 C0  = {0,0,0,0}, C1  = {0,0,0,0}, C2  = {0,0,0,0}, C3  = {0,0,0,0};
        float4 C4  = {0,0,0,0}, C5  = {0,0,0,0}, C6  = {0,0,0,0}, C7  = {0,0,0,0};
        float4 C8  = {0,0,0,0}, C9  = {0,0,0,0}, C10 = {0,0,0,0}, C11 = {0,0,0,0};
        float4 C12 = {0,0,0,0}, C13 = {0,0,0,0}, C14 = {0,0,0,0}, C15 = {0,0,0,0};

        uint2 a0 = *(const uint2*)(aR);
        uint2 a1 = *(const uint2*)(aR +  8 * AW);
        uint2 a2 = *(const uint2*)(aR + 16 * AW);
        uint2 a3 = *(const uint2*)(aR + 24 * AW);

        #pragma unroll
        for (int ch = 0; ch < 16; ++ch) {
            uint2 n0, n1, n2, n3;
            if (ch < 15) {
                const int no = (ch + 1) * 8;
                n0 = *(const uint2*)(aR + no);
                n1 = *(const uint2*)(aR +  8 * AW + no);
                n2 = *(const uint2*)(aR + 16 * AW + no);
                n3 = *(const uint2*)(aR + 24 * AW + no);
            }
            const int bof = ch * 8 + 2 * kq;
#define BMMAQ(nt, nt8) { uint2 bb = *(const uint2*)&sB[((cg * 8 + (nt)) * 8 + lam) * BSTR2 + bof]; \
            MMA_F16(C##nt,  a0.x, a1.x, a0.y, a1.y, bb.x, bb.y);              \
            MMA_F16(C##nt8, a2.x, a3.x, a2.y, a3.y, bb.x, bb.y); }
            BMMAQ(0, 8) BMMAQ(1, 9) BMMAQ(2, 10) BMMAQ(3, 11)
            BMMAQ(4, 12) BMMAQ(5, 13) BMMAQ(6, 14) BMMAQ(7, 15)
#undef BMMAQ
            if (ch < 15) { a0 = n0; a1 = n1; a2 = n2; a3 = n3; }
        }

        float rs0 = 0.f, rs1 = 0.f, rs2 = 0.f, rs3 = 0.f;
#define EPI2(nt, nt8) { const int c0i = cg * 64 + (nt) * 8 + kq * 2;              \
    const float w0 = sW3[c0i], w1 = sW3[c0i + 1];                                 \
    const float z0 = sB2[c0i], z1 = sB2[c0i + 1];                                 \
    rs0 += mish_f(C##nt.x  + z0) * w0 + mish_f(C##nt.y  + z1) * w1;               \
    rs1 += mish_f(C##nt.z  + z0) * w0 + mish_f(C##nt.w  + z1) * w1;               \
    rs2 += mish_f(C##nt8.x + z0) * w0 + mish_f(C##nt8.y + z1) * w1;               \
    rs3 += mish_f(C##nt8.z + z0) * w0 + mish_f(C##nt8.w + z1) * w1; }
        EPI2(0, 8) EPI2(1, 9) EPI2(2, 10) EPI2(3, 11)
        EPI2(4, 12) EPI2(5, 13) EPI2(6, 14) EPI2(7, 15)
#undef EPI2
        rs0 += __shfl_xor_sync(0xffffffffu, rs0, 1);
        rs0 += __shfl_xor_sync(0xffffffffu, rs0, 2);
        rs1 += __shfl_xor_sync(0xffffffffu, rs1, 1);
        rs1 += __shfl_xor_sync(0xffffffffu, rs1, 2);
        rs2 += __shfl_xor_sync(0xffffffffu, rs2, 1);
        rs2 += __shfl_xor_sync(0xffffffffu, rs2, 2);
        rs3 += __shfl_xor_sync(0xffffffffu, rs3, 1);
        rs3 += __shfl_xor_sync(0xffffffffu, rs3, 2);
        if (kq == 0) {
            sRowP[(r0)      * 2 + cg] = rs0;
            sRowP[(r0 +  8) * 2 + cg] = rs1;
            sRowP[(r0 + 16) * 2 + cg] = rs2;
            sRowP[(r0 + 24) * 2 + cg] = rs3;
        }
    }
    __syncthreads();

    {
        const int i = tid & 7, su = tid >> 3;
        int r0 = sPerm[su * 8 + i] * 64 + su;
        int r1 = sPerm[(su + 32) * 8 + i] * 64 + su + 32;
        sRed[tid] = sRowP[2 * r0] + sRowP[2 * r0 + 1]
                  + sRowP[2 * r1] + sRowP[2 * r1 + 1] + b3v;
    }
    __syncthreads();
    if (tid < 8) {
        float sum = 0.0f;
        #pragma unroll 8
        for (int g = 0; g < 32; ++g) sum += sRed[g * 8 + tid];
        float q = sum * (1.0f / 64.0f);
        atomicAdd(&out[b * Nc + tid], q);                 // q1
        atomicAdd(&out[Bc * Nc + b * Nc + tid], q);       // duplicate half
    }
}

extern "C" void kernel_launch(void* const* d_in, const int* in_sizes, int n_in,
                              void* d_out, int out_size) {
    const float* state  = (const float*)d_in[0];
    const float* action = (const float*)d_in[1];
    const float* W1     = (const float*)d_in[2];
    const float* b1     = (const float*)d_in[3];
    const float* W2     = (const float*)d_in[4];
    const float* b2     = (const float*)d_in[5];
    const float* W3     = (const float*)d_in[6];
    const float* b3     = (const float*)d_in[7];
    const int*   perm   = (const int*)  d_in[8];
    float* out = (float*)d_out;

    cudaFuncSetAttribute(shapley_mma,
                         cudaFuncAttributeMaxDynamicSharedMemorySize, SMEM_MAIN);
    cudaFuncSetAttribute(prep_bA_kernel,
                         cudaFuncAttributeMaxDynamicSharedMemorySize, PB_SMEM);

    prep_w2_kernel<<<128, 256>>>(W2);
    prep_bA_kernel<<<Bc, 512, PB_SMEM>>>(state, action, W1, b1, perm);

    int zelems = (out_size < 2 * Bc * Nc) ? out_size : (2 * Bc * Nc);
    cudaMemsetAsync(d_out, 0, (size_t)zelems * sizeof(float), 0);

    shapley_mma<<<Bc * 2, 256, SMEM_MAIN>>>(b2, W3, b3, perm, out);
}

// round 16
// speedup vs baseline: 1.1808x; 1.0370x over previous
#include <cuda_runtime.h>
#include <cuda_fp16.h>
#include <cstdint>

// ---------------- problem shapes ----------------
#define Bc   512
#define Sc   64
#define Nc   8
#define Ac   16
#define Hc   256
#define OBSc 512

// strides (32-bit words)
#define BSTR2 136    // uint32 words per B column (16 chunks * 8 + pad 8)
#define AW    128    // uint32 words per A row in gmem

// ---------------- device scratch ----------------
__device__ __align__(16) uint32_t g_B16[2][128 * BSTR2];      // fp16x2 W2 image per n-half
__device__ __align__(16) uint32_t g_A[(size_t)Bc * 512 * AW]; // fp16x2 A, chunk-pair layout

// ---------------- helpers ----------------
__device__ __forceinline__ float mish_f(float x) {
    float e  = __expf(fminf(x, 15.0f));
    float u  = 1.0f + e;
    float d  = fmaf(u, u, 1.0f);
    float r  = __uint_as_float(0x7EF477D5u - __float_as_uint(d));
    r = r * (2.0f - d * r);
    r = r * (2.0f - d * r);
    return x * (1.0f - 2.0f * r);
}
__device__ __forceinline__ uint32_t h2pack(float lo, float hi) {
    uint32_t r;
    asm("cvt.rn.f16x2.f32 %0, %1, %2;" : "=r"(r) : "f"(hi), "f"(lo));
    return r;
}

#define MMA_F16(C, a0, a1, a2, a3, b0, b1)                                    \
    asm volatile("mma.sync.aligned.m16n8k16.row.col.f32.f16.f16.f32 "        \
        "{%0,%1,%2,%3}, {%4,%5,%6,%7}, {%8,%9}, {%0,%1,%2,%3};"              \
        : "+f"(C.x), "+f"(C.y), "+f"(C.z), "+f"(C.w)                         \
        : "r"(a0), "r"(a1), "r"(a2), "r"(a3), "r"(b0), "r"(b1))

// ================= prep 1: W2 -> fp16x2 packed B images =================
__global__ void prep_w2_kernel(const float* __restrict__ W2) {
    int idx = blockIdx.x * blockDim.x + threadIdx.x;   // 32768 words
    if (idx >= 2 * 128 * 128) return;
    int nhalf = idx >> 14;
    int rem   = idx & 16383;
    int col   = rem >> 7;
    int w     = rem & 127;
    int chunk = w >> 3;
    int kq    = (w >> 1) & 3;
    int hi    = w & 1;
    int k0    = chunk * 16 + hi * 8 + kq * 2;
    int n     = nhalf * 128 + col;
    g_B16[nhalf][col * BSTR2 + w] = h2pack(W2[k0 * Hc + n], W2[(k0 + 1) * Hc + n]);
}

// ================= merged prep: obs1 + PA (smem) -> A = mish(prefix) fp16 ====
// grid 512 (one b), 512 threads. Thread = (hg = tid&63 -> 4 h cols, seg = tid>>6).
// A row word layout (chunk-pair): w = cp*16 + kq*4 + t2,
//   ch = 2*cp + (t2>>1), hi = t2&1, k0 = ch*16 + hi*8 + kq*2.
#define PB_SMEM ((512 + 128 + 2048 + 64 * 256 + 512) * 4)   // 78336 B
__global__ void __launch_bounds__(512, 2)
prep_bA_kernel(const float* __restrict__ state,
               const float* __restrict__ action,
               const float* __restrict__ W1,
               const float* __restrict__ b1,
               const int*   __restrict__ perm) {
    extern __shared__ float pbs[];
    float* sState = pbs;                            // 512
    float* sAct   = pbs + 512;                      // 128
    float* sObsP  = pbs + 640;                      // 8 segs x 256 h
    float* sPA    = pbs + 2688;                     // 64*256
    int*   sPerm  = (int*)(pbs + 2688 + 64 * 256);  // 512
    const int tid = threadIdx.x;
    const int b   = blockIdx.x;

    sState[tid] = state[b * OBSc + tid];
    if (tid < 128) sAct[tid] = action[b * 128 + tid];
    sPerm[tid] = perm[b * 512 + tid];
    __syncthreads();

    const int hg  = tid & 63;       // h group: h0 = hg*4
    const int seg = tid >> 6;       // 0..7
    const int h0  = hg * 4;

    // ---- obs1 partials: seg covers k in [seg*64, seg*64+64) ----
    {
        float p0 = 0.f, p1 = 0.f, p2 = 0.f, p3 = 0.f;
        const int kb = seg * 64;
        #pragma unroll 4
        for (int k = kb; k < kb + 64; ++k) {
            const float4 w = *(const float4*)&W1[k * Hc + h0];
            const float s = sState[k];
            p0 = fmaf(s, w.x, p0);
            p1 = fmaf(s, w.y, p1);
            p2 = fmaf(s, w.z, p2);
            p3 = fmaf(s, w.w, p3);
        }
        sObsP[seg * 256 + h0]     = p0;
        sObsP[seg * 256 + h0 + 1] = p1;
        sObsP[seg * 256 + h0 + 2] = p2;
        sObsP[seg * 256 + h0 + 3] = p3;
    }
    __syncthreads();

    // ---- ob4 = b1 + sum of 8 partials ----
    float4 ob4 = *(const float4*)&b1[h0];
    #pragma unroll
    for (int sg = 0; sg < 8; ++sg) {
        ob4.x += sObsP[sg * 256 + h0];
        ob4.y += sObsP[sg * 256 + h0 + 1];
        ob4.z += sObsP[sg * 256 + h0 + 2];
        ob4.w += sObsP[sg * 256 + h0 + 3];
    }

    // ---- PA rows: thread's j = seg; W1 row reused across 8 n ----
    {
        const int j = seg;
        float4 pa0 = {0,0,0,0}, pa1 = {0,0,0,0}, pa2 = {0,0,0,0}, pa3 = {0,0,0,0};
        float4 pa4 = {0,0,0,0}, pa5 = {0,0,0,0}, pa6 = {0,0,0,0}, pa7 = {0,0,0,0};
        #pragma unroll
        for (int k = 0; k < 16; ++k) {
            const float4 w = *(const float4*)&W1[(OBSc + j * 16 + k) * Hc + h0];
#define PACC(n) { const float a = sAct[(n) * 16 + k];                          \
    pa##n.x = fmaf(a, w.x, pa##n.x); pa##n.y = fmaf(a, w.y, pa##n.y);          \
    pa##n.z = fmaf(a, w.z, pa##n.z); pa##n.w = fmaf(a, w.w, pa##n.w); }
            PACC(0) PACC(1) PACC(2) PACC(3) PACC(4) PACC(5) PACC(6) PACC(7)
#undef PACC
        }
        if (j == 0) {
#define FOLD(n) { pa##n.x += ob4.x; pa##n.y += ob4.y;                          \
                  pa##n.z += ob4.z; pa##n.w += ob4.w; }
            FOLD(0) FOLD(1) FOLD(2) FOLD(3) FOLD(4) FOLD(5) FOLD(6) FOLD(7)
#undef FOLD
        }
#define PST(n) *(float4*)&sPA[(j * 8 + (n)) * 256 + h0] = pa##n;
        PST(0) PST(1) PST(2) PST(3) PST(4) PST(5) PST(6) PST(7)
#undef PST
    }
    __syncthreads();

    // ---- prefix + mish + fp16 pack -> g_A (chunk-pair word layout) ----
    const int quarter = tid >> 7;    // 0..3 -> s block of 16
    const int wp      = tid & 127;   // word position in A row
    const int cp      = wp >> 4;
    const int kq      = (wp >> 2) & 3;
    const int t2      = wp & 3;
    const int ch      = cp * 2 + (t2 >> 1);
    const int hi      = t2 & 1;
    const int k0      = ch * 16 + hi * 8 + kq * 2;

    #pragma unroll 2
    for (int ss = 0; ss < 16; ++ss) {
        const int s = quarter * 16 + ss;
        float x0 = 0.f, x1 = 0.f;
        #pragma unroll
        for (int t = 0; t < 8; ++t) {
            const int row = t * 8 + sPerm[s * 8 + t];
            float2 v = *(const float2*)&sPA[row * 256 + k0];
            x0 += v.x; x1 += v.y;
            g_A[((size_t)b * 512 + t * 64 + s) * AW + wp] =
                h2pack(mish_f(x0), mish_f(x1));
        }
    }
}

// ================= main fused GEMM kernel =================
// grid 1024: (b = bx>>1, nh = bx&1). 256 threads, 8 warps, 2 CTAs/SM.
// Warp tile: 32 rows x 64 cols (rg = wid>>1, cg = wid&1); 4 passes of 128 rows.
// A fragments: one LDG.128 per row per chunk-pair (2-chunk prefetch distance).
#define OFF_B     0
#define SZ_B      (128 * BSTR2 * 4)        // 69632
#define OFF_PERM  (OFF_B + SZ_B)           // 512 ints
#define OFF_ROWP  (OFF_PERM + 2048)        // 512*2 f
#define OFF_B2    (OFF_ROWP + 4096)        // 128 f
#define OFF_W3    (OFF_B2 + 512)           // 128 f
#define OFF_RED   (OFF_W3 + 512)           // 256 f
#define SMEM_MAIN (OFF_RED + 1024)         // 77824 B -> 2 CTAs/SM

__global__ void __launch_bounds__(256, 2)
shapley_mma(const float* __restrict__ b2,
            const float* __restrict__ W3,
            const float* __restrict__ b3,
            const int*   __restrict__ perm,
            float*       __restrict__ out) {
    extern __shared__ char smem[];
    const int tid  = threadIdx.x;
    const int wid  = tid >> 5;
    const int lane = tid & 31;
    const int b    = blockIdx.x >> 1;
    const int nh   = blockIdx.x & 1;

    uint32_t* sB = (uint32_t*)(smem + OFF_B);
    int*   sPerm = (int*)  (smem + OFF_PERM);
    float* sRowP = (float*)(smem + OFF_ROWP);
    float* sB2   = (float*)(smem + OFF_B2);
    float* sW3   = (float*)(smem + OFF_W3);
    float* sRed  = (float*)(smem + OFF_RED);

    {
        const uint4* src = (const uint4*)g_B16[nh];
        uint4* dst = (uint4*)sB;
        for (int i = tid; i < (128 * BSTR2) / 4; i += 256) dst[i] = src[i];
    }
    for (int i = tid; i < Sc * Nc; i += 256) sPerm[i] = perm[b * (Sc * Nc) + i];
    if (tid < 128) {
        sB2[tid] = b2[nh * 128 + tid];
        sW3[tid] = W3[nh * 128 + tid];
    }
    const float b3v = b3[0];
    __syncthreads();

    const int lam = lane >> 2;
    const int kq  = lane & 3;
    const int rg  = wid >> 1;      // 0..3
    const int cg  = wid & 1;       // 0..1

    #pragma unroll 1
    for (int p = 0; p < 4; ++p) {
        const int r0 = p * 128 + rg * 32 + lam;
        // uint4 view of A rows; row stride = AW/4 = 32 uint4
        const uint4* aB = (const uint4*)(g_A + ((size_t)b * 512 + r0) * AW);

        float4 C0  = {0,0,0,0}, C1  = {0,0,0,0}, C2  = {0,0,0,0}, C3  = {0,0,0,0};
        float4 C4  = {0,0,0,0}, C5  = {0,0,0,0}, C6  = {0,0,0,0}, C7  = {0,0,0,0};
        float4 C8  = {0,0,0,0}, C9  = {0,0,0,0}, C10 = {0,0,0,0}, C11 = {0,0,0,0};
        float4 C12 = {0,0,0,0}, C13 = {0,0,0,0}, C14 = {0,0,0,0}, C15 = {0,0,0,0};

        // chunk-pair 0 fragments for rows r0, r0+8, r0+16, r0+24
        uint4 q0 = aB[kq];
        uint4 q1 = aB[8 * 32 + kq];
        uint4 q2 = aB[16 * 32 + kq];
        uint4 q3 = aB[24 * 32 + kq];

        #pragma unroll
        for (int cp = 0; cp < 8; ++cp) {
            uint4 n0, n1, n2, n3;
            if (cp < 7) {                         // compile-time after unroll
                const int no = (cp + 1) * 4 + kq;
                n0 = aB[no];
                n1 = aB[8 * 32 + no];
                n2 = aB[16 * 32 + no];
                n3 = aB[24 * 32 + no];
            }
            // chunk 2cp (fragments .x/.y), then chunk 2cp+1 (.z/.w)
            const int bof0 = (2 * cp) * 8 + 2 * kq;
            const int bof1 = bof0 + 8;
#define BMMAQ(nt, nt8, BO, X, Y) {                                            \
            uint2 bb = *(const uint2*)&sB[((cg * 8 + (nt)) * 8 + lam) * BSTR2 + (BO)]; \
            MMA_F16(C##nt,  q0.X, q1.X, q0.Y, q1.Y, bb.x, bb.y);              \
            MMA_F16(C##nt8, q2.X, q3.X, q2.Y, q3.Y, bb.x, bb.y); }
            BMMAQ(0, 8,  bof0, x, y) BMMAQ(1, 9,  bof0, x, y)
            BMMAQ(2, 10, bof0, x, y) BMMAQ(3, 11, bof0, x, y)
            BMMAQ(4, 12, bof0, x, y) BMMAQ(5, 13, bof0, x, y)
            BMMAQ(6, 14, bof0, x, y) BMMAQ(7, 15, bof0, x, y)
            BMMAQ(0, 8,  bof1, z, w) BMMAQ(1, 9,  bof1, z, w)
            BMMAQ(2, 10, bof1, z, w) BMMAQ(3, 11, bof1, z, w)
            BMMAQ(4, 12, bof1, z, w) BMMAQ(5, 13, bof1, z, w)
            BMMAQ(6, 14, bof1, z, w) BMMAQ(7, 15, bof1, z, w)
#undef BMMAQ
            if (cp < 7) { q0 = n0; q1 = n1; q2 = n2; q3 = n3; }
        }

        float rs0 = 0.f, rs1 = 0.f, rs2 = 0.f, rs3 = 0.f;
#define EPI2(nt, nt8) { const int c0i = cg * 64 + (nt) * 8 + kq * 2;              \
    const float w0 = sW3[c0i], w1 = sW3[c0i + 1];                                 \
    const float z0 = sB2[c0i], z1 = sB2[c0i + 1];                                 \
    rs0 += mish_f(C##nt.x  + z0) * w0 + mish_f(C##nt.y  + z1) * w1;               \
    rs1 += mish_f(C##nt.z  + z0) * w0 + mish_f(C##nt.w  + z1) * w1;               \
    rs2 += mish_f(C##nt8.x + z0) * w0 + mish_f(C##nt8.y + z1) * w1;               \
    rs3 += mish_f(C##nt8.z + z0) * w0 + mish_f(C##nt8.w + z1) * w1; }
        EPI2(0, 8) EPI2(1, 9) EPI2(2, 10) EPI2(3, 11)
        EPI2(4, 12) EPI2(5, 13) EPI2(6, 14) EPI2(7, 15)
#undef EPI2
        rs0 += __shfl_xor_sync(0xffffffffu, rs0, 1);
        rs0 += __shfl_xor_sync(0xffffffffu, rs0, 2);
        rs1 += __shfl_xor_sync(0xffffffffu, rs1, 1);
        rs1 += __shfl_xor_sync(0xffffffffu, rs1, 2);
        rs2 += __shfl_xor_sync(0xffffffffu, rs2, 1);
        rs2 += __shfl_xor_sync(0xffffffffu, rs2, 2);
        rs3 += __shfl_xor_sync(0xffffffffu, rs3, 1);
        rs3 += __shfl_xor_sync(0xffffffffu, rs3, 2);
        if (kq == 0) {
            sRowP[(r0)      * 2 + cg] = rs0;
            sRowP[(r0 +  8) * 2 + cg] = rs1;
            sRowP[(r0 + 16) * 2 + cg] = rs2;
            sRowP[(r0 + 24) * 2 + cg] = rs3;
        }
    }
    __syncthreads();

    {
        const int i = tid & 7, su = tid >> 3;
        int r0 = sPerm[su * 8 + i] * 64 + su;
        int r1 = sPerm[(su + 32) * 8 + i] * 64 + su + 32;
        sRed[tid] = sRowP[2 * r0] + sRowP[2 * r0 + 1]
                  + sRowP[2 * r1] + sRowP[2 * r1 + 1] + b3v;
    }
    __syncthreads();
    if (tid < 8) {
        float sum = 0.0f;
        #pragma unroll 8
        for (int g = 0; g < 32; ++g) sum += sRed[g * 8 + tid];
        float q = sum * (1.0f / 64.0f);
        atomicAdd(&out[b * Nc + tid], q);                 // q1
        atomicAdd(&out[Bc * Nc + b * Nc + tid], q);       // duplicate half
    }
}

extern "C" void kernel_launch(void* const* d_in, const int* in_sizes, int n_in,
                              void* d_out, int out_size) {
    const float* state  = (const float*)d_in[0];
    const float* action = (const float*)d_in[1];
    const float* W1     = (const float*)d_in[2];
    const float* b1     = (const float*)d_in[3];
    const float* W2     = (const float*)d_in[4];
    const float* b2     = (const float*)d_in[5];
    const float* W3     = (const float*)d_in[6];
    const float* b3     = (const float*)d_in[7];
    const int*   perm   = (const int*)  d_in[8];
    float* out = (float*)d_out;

    cudaFuncSetAttribute(shapley_mma,
                         cudaFuncAttributeMaxDynamicSharedMemorySize, SMEM_MAIN);
    cudaFuncSetAttribute(prep_bA_kernel,
                         cudaFuncAttributeMaxDynamicSharedMemorySize, PB_SMEM);

    prep_w2_kernel<<<128, 256>>>(W2);
    prep_bA_kernel<<<Bc, 512, PB_SMEM>>>(state, action, W1, b1, perm);

    int zelems = (out_size < 2 * Bc * Nc) ? out_size : (2 * Bc * Nc);
    cudaMemsetAsync(d_out, 0, (size_t)zelems * sizeof(float), 0);

    shapley_mma<<<Bc * 2, 256, SMEM_MAIN>>>(b2, W3, b3, perm, out);
}

// round 17
// speedup vs baseline: 1.2076x; 1.0227x over previous
#include <cuda_runtime.h>
#include <cuda_fp16.h>
#include <cstdint>

// ---------------- problem shapes ----------------
#define Bc   512
#define Sc   64
#define Nc   8
#define Ac   16
#define Hc   256
#define OBSc 512

// strides (32-bit words)
#define BSTR2 136    // uint32 words per B column (16 chunks * 8 + pad 8)
#define AW    128    // uint32 words per A row in gmem

// ---------------- device scratch ----------------
__device__ __align__(16) uint32_t g_B16[2][128 * BSTR2];      // fp16x2 W2 image per n-half
__device__ __align__(16) uint32_t g_A[(size_t)Bc * 512 * AW]; // fp16x2 A, chunk-pair layout

// ---------------- helpers ----------------
__device__ __forceinline__ float mish_f(float x) {
    float e  = __expf(fminf(x, 15.0f));
    float u  = 1.0f + e;
    float d  = fmaf(u, u, 1.0f);
    float r  = __uint_as_float(0x7EF477D5u - __float_as_uint(d));
    r = r * (2.0f - d * r);
    r = r * (2.0f - d * r);
    return x * (1.0f - 2.0f * r);
}
__device__ __forceinline__ uint32_t h2pack(float lo, float hi) {
    uint32_t r;
    asm("cvt.rn.f16x2.f32 %0, %1, %2;" : "=r"(r) : "f"(hi), "f"(lo));
    return r;
}

#define MMA_F16(C, a0, a1, a2, a3, b0, b1)                                    \
    asm volatile("mma.sync.aligned.m16n8k16.row.col.f32.f16.f16.f32 "        \
        "{%0,%1,%2,%3}, {%4,%5,%6,%7}, {%8,%9}, {%0,%1,%2,%3};"              \
        : "+f"(C.x), "+f"(C.y), "+f"(C.z), "+f"(C.w)                         \
        : "r"(a0), "r"(a1), "r"(a2), "r"(a3), "r"(b0), "r"(b1))

// ================= prep 1: W2 -> fp16x2 packed B images =================
__global__ void prep_w2_kernel(const float* __restrict__ W2) {
    int idx = blockIdx.x * blockDim.x + threadIdx.x;   // 32768 words
    if (idx >= 2 * 128 * 128) return;
    int nhalf = idx >> 14;
    int rem   = idx & 16383;
    int col   = rem >> 7;
    int w     = rem & 127;
    int chunk = w >> 3;
    int kq    = (w >> 1) & 3;
    int hi    = w & 1;
    int k0    = chunk * 16 + hi * 8 + kq * 2;
    int n     = nhalf * 128 + col;
    g_B16[nhalf][col * BSTR2 + w] = h2pack(W2[k0 * Hc + n], W2[(k0 + 1) * Hc + n]);
}

// ================= merged prep: 4 b per block, W1 amortized =================
// grid 128, 512 threads, 1 block/SM (186 KB smem).
// smem floats: sState 2048 | sAct 512 | sPerm 2048i | sObsP 8192 | sObs 1024 |
//              sPA 2*64*256 = 32768  -> total 46592 f = 186368 B
#define PB2_FLOATS 46592
#define PB2_SMEM   (PB2_FLOATS * 4)
__global__ void __launch_bounds__(512, 1)
prep_bA_kernel(const float* __restrict__ state,
               const float* __restrict__ action,
               const float* __restrict__ W1,
               const float* __restrict__ b1,
               const int*   __restrict__ perm) {
    extern __shared__ float pbs[];
    float* sState = pbs;                   // 4 x 512
    float* sAct   = pbs + 2048;            // 4 x 128
    int*   sPerm  = (int*)(pbs + 2560);    // 4 x 512
    float* sObsP  = pbs + 4608;            // 8 segs x 4 b x 256 h
    float* sObs   = pbs + 12800;           // 4 b x 256 h
    float* sPA    = pbs + 13824;           // 2 b x 64 x 256
    const int tid = threadIdx.x;
    const int b0  = blockIdx.x * 4;

    #pragma unroll
    for (int i = 0; i < 4; ++i)
        sState[tid + i * 512] = state[b0 * OBSc + tid + i * 512];
    sAct[tid & 511] = action[b0 * 128 + (tid & 511)];   // 512 = 4*128
    #pragma unroll
    for (int i = 0; i < 4; ++i)
        sPerm[tid + i * 512] = perm[b0 * 512 + tid + i * 512];
    __syncthreads();

    const int hg  = tid & 63;       // h0 = hg*4
    const int seg = tid >> 6;       // 0..7
    const int h0  = hg * 4;

    // ---- obs partials for 4 b at once: seg covers k in [seg*64, seg*64+64) ----
    {
        float4 oA = {0,0,0,0}, oB = {0,0,0,0}, oC = {0,0,0,0}, oD = {0,0,0,0};
        const int kb = seg * 64;
        #pragma unroll 4
        for (int k = kb; k < kb + 64; ++k) {
            const float4 w = *(const float4*)&W1[k * Hc + h0];
            const float s0 = sState[k];
            const float s1 = sState[512 + k];
            const float s2 = sState[1024 + k];
            const float s3 = sState[1536 + k];
            oA.x = fmaf(s0, w.x, oA.x); oA.y = fmaf(s0, w.y, oA.y);
            oA.z = fmaf(s0, w.z, oA.z); oA.w = fmaf(s0, w.w, oA.w);
            oB.x = fmaf(s1, w.x, oB.x); oB.y = fmaf(s1, w.y, oB.y);
            oB.z = fmaf(s1, w.z, oB.z); oB.w = fmaf(s1, w.w, oB.w);
            oC.x = fmaf(s2, w.x, oC.x); oC.y = fmaf(s2, w.y, oC.y);
            oC.z = fmaf(s2, w.z, oC.z); oC.w = fmaf(s2, w.w, oC.w);
            oD.x = fmaf(s3, w.x, oD.x); oD.y = fmaf(s3, w.y, oD.y);
            oD.z = fmaf(s3, w.z, oD.z); oD.w = fmaf(s3, w.w, oD.w);
        }
        *(float4*)&sObsP[seg * 1024 + 0 * 256 + h0] = oA;
        *(float4*)&sObsP[seg * 1024 + 1 * 256 + h0] = oB;
        *(float4*)&sObsP[seg * 1024 + 2 * 256 + h0] = oC;
        *(float4*)&sObsP[seg * 1024 + 3 * 256 + h0] = oD;
    }
    __syncthreads();

    // ---- reduce 8 segs -> sObs[bq*256 + h] (2 items per thread) ----
    #pragma unroll
    for (int r = 0; r < 2; ++r) {
        const int item = tid + r * 512;          // item = bq*256 + h
        float v = b1[item & 255];
        #pragma unroll
        for (int sg = 0; sg < 8; ++sg) v += sObsP[sg * 1024 + item];
        sObs[item] = v;
    }
    __syncthreads();

    // ---- two halves: PA (fp32) for 2 b, then prefix+mish+write ----
    #pragma unroll 1
    for (int h2 = 0; h2 < 2; ++h2) {
        // PA for b = b0 + h2*2 + bq2, thread's j = seg
        #pragma unroll 1
        for (int bq2 = 0; bq2 < 2; ++bq2) {
            const int bq = h2 * 2 + bq2;
            const int j  = seg;
            float4 pa0 = {0,0,0,0}, pa1 = {0,0,0,0}, pa2 = {0,0,0,0}, pa3 = {0,0,0,0};
            float4 pa4 = {0,0,0,0}, pa5 = {0,0,0,0}, pa6 = {0,0,0,0}, pa7 = {0,0,0,0};
            #pragma unroll
            for (int k = 0; k < 16; ++k) {
                const float4 w = *(const float4*)&W1[(OBSc + j * 16 + k) * Hc + h0];
#define PACC(n) { const float a = sAct[bq * 128 + (n) * 16 + k];               \
    pa##n.x = fmaf(a, w.x, pa##n.x); pa##n.y = fmaf(a, w.y, pa##n.y);          \
    pa##n.z = fmaf(a, w.z, pa##n.z); pa##n.w = fmaf(a, w.w, pa##n.w); }
                PACC(0) PACC(1) PACC(2) PACC(3) PACC(4) PACC(5) PACC(6) PACC(7)
#undef PACC
            }
            if (j == 0) {
                const float4 ob4 = *(const float4*)&sObs[bq * 256 + h0];
#define FOLD(n) { pa##n.x += ob4.x; pa##n.y += ob4.y;                          \
                  pa##n.z += ob4.z; pa##n.w += ob4.w; }
                FOLD(0) FOLD(1) FOLD(2) FOLD(3) FOLD(4) FOLD(5) FOLD(6) FOLD(7)
#undef FOLD
            }
#define PST(n) *(float4*)&sPA[bq2 * 16384 + (j * 8 + (n)) * 256 + h0] = pa##n;
            PST(0) PST(1) PST(2) PST(3) PST(4) PST(5) PST(6) PST(7)
#undef PST
        }
        __syncthreads();

        // prefix + mish + fp16 pack -> g_A (chunk-pair word layout)
        const int b2    = tid >> 8;          // 0/1 within half
        const int local = tid & 255;
        const int wp    = local & 127;
        const int sh    = local >> 7;        // s block of 32
        const int cp    = wp >> 4;
        const int kq    = (wp >> 2) & 3;
        const int t2    = wp & 3;
        const int ch    = cp * 2 + (t2 >> 1);
        const int hi    = t2 & 1;
        const int k0    = ch * 16 + hi * 8 + kq * 2;
        const int bb    = h2 * 2 + b2;       // b index within block

        #pragma unroll 2
        for (int ss = 0; ss < 32; ++ss) {
            const int s = sh * 32 + ss;
            float x0 = 0.f, x1 = 0.f;
            #pragma unroll
            for (int t = 0; t < 8; ++t) {
                const int row = t * 8 + sPerm[bb * 512 + s * 8 + t];
                float2 v = *(const float2*)&sPA[b2 * 16384 + row * 256 + k0];
                x0 += v.x; x1 += v.y;
                g_A[((size_t)(b0 + bb) * 512 + t * 64 + s) * AW + wp] =
                    h2pack(mish_f(x0), mish_f(x1));
            }
        }
        if (h2 == 0) __syncthreads();   // sPA reads done before next half's writes
    }
}

// ================= main fused GEMM kernel (R15, unchanged) =================
#define OFF_B     0
#define SZ_B      (128 * BSTR2 * 4)        // 69632
#define OFF_PERM  (OFF_B + SZ_B)           // 512 ints
#define OFF_ROWP  (OFF_PERM + 2048)        // 512*2 f
#define OFF_B2    (OFF_ROWP + 4096)        // 128 f
#define OFF_W3    (OFF_B2 + 512)           // 128 f
#define OFF_RED   (OFF_W3 + 512)           // 256 f
#define SMEM_MAIN (OFF_RED + 1024)         // 77824 B -> 2 CTAs/SM

__global__ void __launch_bounds__(256, 2)
shapley_mma(const float* __restrict__ b2,
            const float* __restrict__ W3,
            const float* __restrict__ b3,
            const int*   __restrict__ perm,
            float*       __restrict__ out) {
    extern __shared__ char smem[];
    const int tid  = threadIdx.x;
    const int wid  = tid >> 5;
    const int lane = tid & 31;
    const int b    = blockIdx.x >> 1;
    const int nh   = blockIdx.x & 1;

    uint32_t* sB = (uint32_t*)(smem + OFF_B);
    int*   sPerm = (int*)  (smem + OFF_PERM);
    float* sRowP = (float*)(smem + OFF_ROWP);
    float* sB2   = (float*)(smem + OFF_B2);
    float* sW3   = (float*)(smem + OFF_W3);
    float* sRed  = (float*)(smem + OFF_RED);

    {
        const uint4* src = (const uint4*)g_B16[nh];
        uint4* dst = (uint4*)sB;
        for (int i = tid; i < (128 * BSTR2) / 4; i += 256) dst[i] = src[i];
    }
    for (int i = tid; i < Sc * Nc; i += 256) sPerm[i] = perm[b * (Sc * Nc) + i];
    if (tid < 128) {
        sB2[tid] = b2[nh * 128 + tid];
        sW3[tid] = W3[nh * 128 + tid];
    }
    const float b3v = b3[0];
    __syncthreads();

    const int lam = lane >> 2;
    const int kq  = lane & 3;
    const int rg  = wid >> 1;      // 0..3
    const int cg  = wid & 1;       // 0..1

    #pragma unroll 1
    for (int p = 0; p < 4; ++p) {
        const int r0 = p * 128 + rg * 32 + lam;
        const uint4* aB = (const uint4*)(g_A + ((size_t)b * 512 + r0) * AW);

        float4 C0  = {0,0,0,0}, C1  = {0,0,0,0}, C2  = {0,0,0,0}, C3  = {0,0,0,0};
        float4 C4  = {0,0,0,0}, C5  = {0,0,0,0}, C6  = {0,0,0,0}, C7  = {0,0,0,0};
        float4 C8  = {0,0,0,0}, C9  = {0,0,0,0}, C10 = {0,0,0,0}, C11 = {0,0,0,0};
        float4 C12 = {0,0,0,0}, C13 = {0,0,0,0}, C14 = {0,0,0,0}, C15 = {0,0,0,0};

        uint4 q0 = aB[kq];
        uint4 q1 = aB[8 * 32 + kq];
        uint4 q2 = aB[16 * 32 + kq];
        uint4 q3 = aB[24 * 32 + kq];

        #pragma unroll
        for (int cp = 0; cp < 8; ++cp) {
            uint4 n0, n1, n2, n3;
            if (cp < 7) {
                const int no = (cp + 1) * 4 + kq;
                n0 = aB[no];
                n1 = aB[8 * 32 + no];
                n2 = aB[16 * 32 + no];
                n3 = aB[24 * 32 + no];
            }
            const int bof0 = (2 * cp) * 8 + 2 * kq;
            const int bof1 = bof0 + 8;
#define BMMAQ(nt, nt8, BO, X, Y) {                                            \
            uint2 bb = *(const uint2*)&sB[((cg * 8 + (nt)) * 8 + lam) * BSTR2 + (BO)]; \
            MMA_F16(C##nt,  q0.X, q1.X, q0.Y, q1.Y, bb.x, bb.y);              \
            MMA_F16(C##nt8, q2.X, q3.X, q2.Y, q3.Y, bb.x, bb.y); }
            BMMAQ(0, 8,  bof0, x, y) BMMAQ(1, 9,  bof0, x, y)
            BMMAQ(2, 10, bof0, x, y) BMMAQ(3, 11, bof0, x, y)
            BMMAQ(4, 12, bof0, x, y) BMMAQ(5, 13, bof0, x, y)
            BMMAQ(6, 14, bof0, x, y) BMMAQ(7, 15, bof0, x, y)
            BMMAQ(0, 8,  bof1, z, w) BMMAQ(1, 9,  bof1, z, w)
            BMMAQ(2, 10, bof1, z, w) BMMAQ(3, 11, bof1, z, w)
            BMMAQ(4, 12, bof1, z, w) BMMAQ(5, 13, bof1, z, w)
            BMMAQ(6, 14, bof1, z, w) BMMAQ(7, 15, bof1, z, w)
#undef BMMAQ
            if (cp < 7) { q0 = n0; q1 = n1; q2 = n2; q3 = n3; }
        }

        float rs0 = 0.f, rs1 = 0.f, rs2 = 0.f, rs3 = 0.f;
#define EPI2(nt, nt8) { const int c0i = cg * 64 + (nt) * 8 + kq * 2;              \
    const float w0 = sW3[c0i], w1 = sW3[c0i + 1];                                 \
    const float z0 = sB2[c0i], z1 = sB2[c0i + 1];                                 \
    rs0 += mish_f(C##nt.x  + z0) * w0 + mish_f(C##nt.y  + z1) * w1;               \
    rs1 += mish_f(C##nt.z  + z0) * w0 + mish_f(C##nt.w  + z1) * w1;               \
    rs2 += mish_f(C##nt8.x + z0) * w0 + mish_f(C##nt8.y + z1) * w1;               \
    rs3 += mish_f(C##nt8.z + z0) * w0 + mish_f(C##nt8.w + z1) * w1; }
        EPI2(0, 8) EPI2(1, 9) EPI2(2, 10) EPI2(3, 11)
        EPI2(4, 12) EPI2(5, 13) EPI2(6, 14) EPI2(7, 15)
#undef EPI2
        rs0 += __shfl_xor_sync(0xffffffffu, rs0, 1);
        rs0 += __shfl_xor_sync(0xffffffffu, rs0, 2);
        rs1 += __shfl_xor_sync(0xffffffffu, rs1, 1);
        rs1 += __shfl_xor_sync(0xffffffffu, rs1, 2);
        rs2 += __shfl_xor_sync(0xffffffffu, rs2, 1);
        rs2 += __shfl_xor_sync(0xffffffffu, rs2, 2);
        rs3 += __shfl_xor_sync(0xffffffffu, rs3, 1);
        rs3 += __shfl_xor_sync(0xffffffffu, rs3, 2);
        if (kq == 0) {
            sRowP[(r0)      * 2 + cg] = rs0;
            sRowP[(r0 +  8) * 2 + cg] = rs1;
            sRowP[(r0 + 16) * 2 + cg] = rs2;
            sRowP[(r0 + 24) * 2 + cg] = rs3;
        }
    }
    __syncthreads();

    {
        const int i = tid & 7, su = tid >> 3;
        int r0 = sPerm[su * 8 + i] * 64 + su;
        int r1 = sPerm[(su + 32) * 8 + i] * 64 + su + 32;
        sRed[tid] = sRowP[2 * r0] + sRowP[2 * r0 + 1]
                  + sRowP[2 * r1] + sRowP[2 * r1 + 1] + b3v;
    }
    __syncthreads();
    if (tid < 8) {
        float sum = 0.0f;
        #pragma unroll 8
        for (int g = 0; g < 32; ++g) sum += sRed[g * 8 + tid];
        float q = sum * (1.0f / 64.0f);
        atomicAdd(&out[b * Nc + tid], q);                 // q1
        atomicAdd(&out[Bc * Nc + b * Nc + tid], q);       // duplicate half
    }
}

extern "C" void kernel_launch(void* const* d_in, const int* in_sizes, int n_in,
                              void* d_out, int out_size) {
    const float* state  = (const float*)d_in[0];
    const float* action = (const float*)d_in[1];
    const float* W1     = (const float*)d_in[2];
    const float* b1     = (const float*)d_in[3];
    const float* W2     = (const float*)d_in[4];
    const float* b2     = (const float*)d_in[5];
    const float* W3     = (const float*)d_in[6];
    const float* b3     = (const float*)d_in[7];
    const int*   perm   = (const int*)  d_in[8];
    float* out = (float*)d_out;

    cudaFuncSetAttribute(shapley_mma,
                         cudaFuncAttributeMaxDynamicSharedMemorySize, SMEM_MAIN);
    cudaFuncSetAttribute(prep_bA_kernel,
                         cudaFuncAttributeMaxDynamicSharedMemorySize, PB2_SMEM);

    prep_w2_kernel<<<128, 256>>>(W2);
    prep_bA_kernel<<<128, 512, PB2_SMEM>>>(state, action, W1, b1, perm);

    int zelems = (out_size < 2 * Bc * Nc) ? out_size : (2 * Bc * Nc);
    cudaMemsetAsync(d_out, 0, (size_t)zelems * sizeof(float), 0);

    shapley_mma<<<Bc * 2, 256, SMEM_MAIN>>>(b2, W3, b3, perm, out);
}